// round 12
// baseline (speedup 1.0000x reference)
#include <cuda_runtime.h>

#define D     64
#define EPSV  0.1f
#define MAXN  225000
#define MAXE  3200000
#define NBLK  512

// Scratch (no allocations allowed). Zero-initialized at module load.
// INVARIANT: g_deg is all-zero on entry to kernel_launch; gather<2>
// re-zeroes it, so the invariant holds across calls/graph replays.
// Row MAXN (== N) of g_xA/g_xB is the dummy zero row (never written).
__device__ float        g_xA[(MAXN + 1) * D];  // prescaled layer input
__device__ float        g_xB[(MAXN + 1) * D];
__device__ float        g_dinv[MAXN];     // 1/sqrt(deg)  (0 for deg==0)
__device__ float        g_dsq[MAXN];      // sqrt(deg)    (0 for deg==0)
__device__ unsigned int g_deg[MAXN];
__device__ unsigned int g_bsum[NBLK];
__device__ unsigned int g_boff[NBLK];
__device__ int          g_rowptr[MAXN + 1];
__device__ int          g_cursor[MAXN];
__device__ int          g_col[MAXE];      // CSR columns (src node per edge)

// ---------------------------------------------------------------------------
__global__ void deg_kernel(const int* __restrict__ dst, int E) {
    int e = blockIdx.x * blockDim.x + threadIdx.x;
    if (e < E) atomicAdd(&g_deg[dst[e]], 1u);
}

// ---------------------------------------------------------------------------
// Coalesced 3-kernel exclusive scan of g_deg -> g_rowptr/g_cursor (+dinv/dsq).
// ---------------------------------------------------------------------------
__global__ void tile_reduce(int N) {
    int i = blockIdx.x * 1024 + threadIdx.x;
    int lane = threadIdx.x & 31, wid = threadIdx.x >> 5;
    unsigned v = (i < N) ? g_deg[i] : 0u;
    #pragma unroll
    for (int o = 16; o; o >>= 1) v += __shfl_down_sync(0xFFFFFFFFu, v, o);
    __shared__ unsigned ws[32];
    if (lane == 0) ws[wid] = v;
    __syncthreads();
    if (wid == 0) {
        v = ws[lane];
        #pragma unroll
        for (int o = 16; o; o >>= 1) v += __shfl_down_sync(0xFFFFFFFFu, v, o);
        if (lane == 0) g_bsum[blockIdx.x] = v;
    }
}

__global__ void scan_bsums(int B) {           // single block, 1024 threads
    __shared__ unsigned sh[1024];
    int tid = threadIdx.x;
    unsigned v = (tid < B) ? g_bsum[tid] : 0u;
    sh[tid] = v;
    __syncthreads();
    for (int off = 1; off < 1024; off <<= 1) {
        unsigned t = (tid >= off) ? sh[tid - off] : 0u;
        __syncthreads();
        sh[tid] += t;
        __syncthreads();
    }
    if (tid < B) g_boff[tid] = sh[tid] - v;   // exclusive
}

__global__ void emit_rowptr(int N) {
    int b = blockIdx.x, tid = threadIdx.x;
    int lane = tid & 31, wid = tid >> 5;
    int i = b * 1024 + tid;
    unsigned v = (i < N) ? g_deg[i] : 0u;
    unsigned x = v;
    #pragma unroll
    for (int o = 1; o < 32; o <<= 1) {
        unsigned t = __shfl_up_sync(0xFFFFFFFFu, x, o);
        if (lane >= o) x += t;
    }
    __shared__ unsigned wsum[32];
    if (lane == 31) wsum[wid] = x;
    __syncthreads();
    if (wid == 0) {
        unsigned w = wsum[lane], orig = w;
        #pragma unroll
        for (int o = 1; o < 32; o <<= 1) {
            unsigned t = __shfl_up_sync(0xFFFFFFFFu, w, o);
            if (lane >= o) w += t;
        }
        wsum[lane] = w - orig;
    }
    __syncthreads();
    unsigned ex = (x - v) + wsum[wid] + g_boff[b];
    if (i < N) {
        g_rowptr[i] = (int)ex;
        g_cursor[i] = (int)ex;
        float fv = (float)v;
        g_dinv[i] = v ? rsqrtf(fv) : 0.f;
        g_dsq[i]  = v ? sqrtf(fv)  : 0.f;
        if (i == N - 1) g_rowptr[N] = (int)(ex + v);
    }
}

// ---------------------------------------------------------------------------
// fill CSR columns (weights folded into prescaled rows).
// ---------------------------------------------------------------------------
__global__ void fill_kernel(const int* __restrict__ src,
                            const int* __restrict__ dst, int E) {
    int e = blockIdx.x * blockDim.x + threadIdx.x;
    if (e >= E) return;
    int s = __ldg(src + e);
    int d = __ldg(dst + e);
    int pos = atomicAdd(&g_cursor[d], 1);
    g_col[pos] = s;
}

// ---------------------------------------------------------------------------
// prescale: g_xA[n] = dinv[n] * concat(Gu, Gi)[n]   (float4 granularity)
// ---------------------------------------------------------------------------
__global__ void prescale_kernel(const float* __restrict__ Gu,
                                const float* __restrict__ Gi,
                                int U, int N) {
    long long i = (long long)blockIdx.x * blockDim.x + threadIdx.x;
    long long total4 = (long long)N * (D / 4);
    if (i >= total4) return;
    int node = (int)(i >> 4);
    long long ub4 = (long long)U * (D / 4);
    float4 v = (i < ub4) ? ((const float4*)Gu)[i]
                         : ((const float4*)Gi)[i - ub4];
    float di = __ldg(g_dinv + node);
    v.x *= di; v.y *= di; v.z *= di; v.w *= di;
    ((float4*)g_xA)[i] = v;
}

// ---------------------------------------------------------------------------
// Fused gather (unweighted sum of prescaled rows) + dinv_d scale + noise
// perturbation. Warp per node; lane holds float2. Lanes beyond the row end
// substitute sentinel column N (statically-zero dummy row, L1-resident), so
// the inner loop is pure 8-wide with NO serial remainder. Two independent
// accumulators halve the dependency chain.
//   LAYER 0: read g_xA, write g_xB = s0*dinv            (no acc access)
//   LAYER 1: read g_xB, write g_xA = s1*dinv            (no acc access)
//   LAYER 2: read g_xA (gather) + own rows of g_xB/g_xA,
//            acc = (xB[n]*dsq + xA[n]*dsq + s2) / 3, re-zero g_deg
// ---------------------------------------------------------------------------
__device__ __forceinline__ float sgnf(float v) {
    return (v > 0.f) ? 1.f : ((v < 0.f) ? -1.f : 0.f);
}

template <int LAYER>
__global__ void gather_perturb(const float* __restrict__ noise,
                               float* __restrict__ acc, int N) {
    long long t = (long long)blockIdx.x * blockDim.x + threadIdx.x;
    int n = (int)(t >> 5);
    if (n >= N) return;
    int lane = threadIdx.x & 31;

    const float* x = (LAYER == 1) ? g_xB : g_xA;

    int beg = __ldg(g_rowptr + n);
    int end = __ldg(g_rowptr + n + 1);

    // hoist independent loads
    float2 nv = __ldg((const float2*)(noise + (long long)n * D) + lane);
    float  di = __ldg(g_dinv + n);

    float2 sa = make_float2(0.f, 0.f);
    float2 sb = make_float2(0.f, 0.f);
    for (int j0 = beg; j0 < end; j0 += 32) {
        int jj = j0 + lane;
        int col = (jj < end) ? __ldg(g_col + jj) : N;   // sentinel -> zero row
        int cnt  = min(32, end - j0);                   // warp-uniform
        int cnt8 = (cnt + 7) & ~7;
        for (int k = 0; k < cnt8; k += 8) {
            int c0 = __shfl_sync(0xFFFFFFFFu, col, k);
            int c1 = __shfl_sync(0xFFFFFFFFu, col, k + 1);
            int c2 = __shfl_sync(0xFFFFFFFFu, col, k + 2);
            int c3 = __shfl_sync(0xFFFFFFFFu, col, k + 3);
            int c4 = __shfl_sync(0xFFFFFFFFu, col, k + 4);
            int c5 = __shfl_sync(0xFFFFFFFFu, col, k + 5);
            int c6 = __shfl_sync(0xFFFFFFFFu, col, k + 6);
            int c7 = __shfl_sync(0xFFFFFFFFu, col, k + 7);
            float2 v0 = __ldg((const float2*)(x + (long long)c0 * D) + lane);
            float2 v1 = __ldg((const float2*)(x + (long long)c1 * D) + lane);
            float2 v2 = __ldg((const float2*)(x + (long long)c2 * D) + lane);
            float2 v3 = __ldg((const float2*)(x + (long long)c3 * D) + lane);
            float2 v4 = __ldg((const float2*)(x + (long long)c4 * D) + lane);
            float2 v5 = __ldg((const float2*)(x + (long long)c5 * D) + lane);
            float2 v6 = __ldg((const float2*)(x + (long long)c6 * D) + lane);
            float2 v7 = __ldg((const float2*)(x + (long long)c7 * D) + lane);
            sa.x += v0.x; sa.y += v0.y;
            sb.x += v1.x; sb.y += v1.y;
            sa.x += v2.x; sa.y += v2.y;
            sb.x += v3.x; sb.y += v3.y;
            sa.x += v4.x; sa.y += v4.y;
            sb.x += v5.x; sb.y += v5.y;
            sa.x += v6.x; sa.y += v6.y;
            sb.x += v7.x; sb.y += v7.y;
        }
    }
    float2 s = make_float2(sa.x + sb.x, sa.y + sb.y);

    s.x *= di; s.y *= di;

    // perturb: s += sign(s) * (noise_row / max(||noise_row||,1e-12)) * EPS
    float ss = nv.x * nv.x + nv.y * nv.y;
    #pragma unroll
    for (int o = 16; o; o >>= 1) ss += __shfl_xor_sync(0xFFFFFFFFu, ss, o);
    float scale = EPSV / fmaxf(sqrtf(ss), 1e-12f);
    s.x += sgnf(s.x) * nv.x * scale;
    s.y += sgnf(s.y) * nv.y * scale;

    if (LAYER == 0) {
        ((float2*)(g_xB + (long long)n * D))[lane] =
            make_float2(s.x * di, s.y * di);
    } else if (LAYER == 1) {
        ((float2*)(g_xA + (long long)n * D))[lane] =
            make_float2(s.x * di, s.y * di);
    } else {
        // recover s0, s1 from stored prescaled rows: stored * sqrt(deg) ~= s
        float dq = __ldg(g_dsq + n);
        float2 b0 = ((const float2*)(g_xB + (long long)n * D))[lane];
        float2 a1 = ((const float2*)(g_xA + (long long)n * D))[lane];
        const float third = 1.f / 3.f;
        float2 av;
        av.x = (b0.x * dq + a1.x * dq + s.x) * third;
        av.y = (b0.y * dq + a1.y * dq + s.y) * third;
        ((float2*)(acc + (long long)n * D))[lane] = av;
        if (lane == 0) g_deg[n] = 0u;   // restore invariant
    }
}

// ---------------------------------------------------------------------------
extern "C" void kernel_launch(void* const* d_in, const int* in_sizes, int n_in,
                              void* d_out, int out_size) {
    const float* Gu = (const float*)d_in[0];
    const float* Gi = (const float*)d_in[1];
    const float* nz = (const float*)d_in[2];
    const int*   ei = (const int*)d_in[3];

    int U = in_sizes[0] / D;
    int I = in_sizes[1] / D;
    int N = U + I;
    int E = in_sizes[3] / 2;

    const int* src = ei;
    const int* dst = ei + E;
    float* acc = (float*)d_out;

    const int TPB = 256;
    int blks_E = (E + TPB - 1) / TPB;
    int B      = (N + 1023) / 1024;
    long long total4 = (long long)N * (D / 4);
    int blks_p = (int)((total4 + TPB - 1) / TPB);
    long long node_threads = (long long)N * 32;
    int blks_g = (int)((node_threads + TPB - 1) / TPB);

    long long nd = (long long)N * D;

    deg_kernel<<<blks_E, TPB>>>(dst, E);
    tile_reduce<<<B, 1024>>>(N);
    scan_bsums<<<1, 1024>>>(B);
    emit_rowptr<<<B, 1024>>>(N);
    fill_kernel<<<blks_E, TPB>>>(src, dst, E);
    prescale_kernel<<<blks_p, TPB>>>(Gu, Gi, U, N);
    gather_perturb<0><<<blks_g, TPB>>>(nz,          acc, N);
    gather_perturb<1><<<blks_g, TPB>>>(nz + nd,     acc, N);
    gather_perturb<2><<<blks_g, TPB>>>(nz + 2 * nd, acc, N);
}

// round 13
// speedup vs baseline: 1.1419x; 1.1419x over previous
#include <cuda_runtime.h>

#define D     64
#define EPSV  0.1f
#define MAXN  225000
#define MAXE  4000000          // E + 3*N padding headroom
#define NBLK  512

// Scratch (no allocations allowed). Zero-initialized at module load.
// INVARIANT: g_deg is all-zero on entry to kernel_launch; gather<2>
// re-zeroes it, so the invariant holds across calls/graph replays.
__device__ float        g_xA[(MAXN + 1) * D];  // prescaled layer input
__device__ float        g_xB[(MAXN + 1) * D];
__device__ float        g_dinv[MAXN];     // 1/sqrt(deg)  (0 for deg==0)
__device__ float        g_dsq[MAXN];      // sqrt(deg)    (0 for deg==0)
__device__ unsigned int g_deg[MAXN];
__device__ unsigned int g_bsum[NBLK];
__device__ unsigned int g_boff[NBLK];
__device__ int          g_rowptr[MAXN + 1];   // padded offsets (deg rounded to 4)
__device__ int          g_cursor[MAXN];
__device__ int          g_col[MAXE];      // CSR columns (src node per edge)

__device__ __forceinline__ int   ldcs_i(const int* p)   {
    int v; asm("ld.global.cs.b32 %0, [%1];" : "=r"(v) : "l"(p)); return v;
}
__device__ __forceinline__ float2 ldcs_f2(const float2* p) {
    float2 v;
    asm("ld.global.cs.v2.f32 {%0,%1}, [%2];" : "=f"(v.x), "=f"(v.y) : "l"(p));
    return v;
}
__device__ __forceinline__ void stcs_f2(float2* p, float2 v) {
    asm("st.global.cs.v2.f32 [%0], {%1,%2};" :: "l"(p), "f"(v.x), "f"(v.y));
}

// ---------------------------------------------------------------------------
// degree via edge symmetry: edge e (e < E/2) is (u -> i); edge e+E/2 is
// (i -> u). One thread bumps both endpoint degrees.
// ---------------------------------------------------------------------------
__global__ void deg_kernel(const int* __restrict__ ei, int E, int Eh) {
    int e = blockIdx.x * blockDim.x + threadIdx.x;
    if (e >= Eh) return;
    int u = ldcs_i(ei + e);            // src first half  (user)
    int i = ldcs_i(ei + E + e);        // dst first half  (item)
    atomicAdd(&g_deg[u], 1u);
    atomicAdd(&g_deg[i], 1u);
}

// ---------------------------------------------------------------------------
// Coalesced 3-kernel exclusive scan of PADDED degrees -> g_rowptr/g_cursor.
// deg4 = (deg+3) & ~3. dinv/dsq from the real degree.
// ---------------------------------------------------------------------------
__global__ void tile_reduce(int N) {
    int i = blockIdx.x * 1024 + threadIdx.x;
    int lane = threadIdx.x & 31, wid = threadIdx.x >> 5;
    unsigned v = (i < N) ? ((g_deg[i] + 3u) & ~3u) : 0u;
    #pragma unroll
    for (int o = 16; o; o >>= 1) v += __shfl_down_sync(0xFFFFFFFFu, v, o);
    __shared__ unsigned ws[32];
    if (lane == 0) ws[wid] = v;
    __syncthreads();
    if (wid == 0) {
        v = ws[lane];
        #pragma unroll
        for (int o = 16; o; o >>= 1) v += __shfl_down_sync(0xFFFFFFFFu, v, o);
        if (lane == 0) g_bsum[blockIdx.x] = v;
    }
}

__global__ void scan_bsums(int B) {           // single block, 1024 threads
    __shared__ unsigned sh[1024];
    int tid = threadIdx.x;
    unsigned v = (tid < B) ? g_bsum[tid] : 0u;
    sh[tid] = v;
    __syncthreads();
    for (int off = 1; off < 1024; off <<= 1) {
        unsigned t = (tid >= off) ? sh[tid - off] : 0u;
        __syncthreads();
        sh[tid] += t;
        __syncthreads();
    }
    if (tid < B) g_boff[tid] = sh[tid] - v;   // exclusive
}

__global__ void emit_rowptr(int N) {
    int b = blockIdx.x, tid = threadIdx.x;
    int lane = tid & 31, wid = tid >> 5;
    int i = b * 1024 + tid;
    unsigned dreal = (i < N) ? g_deg[i] : 0u;
    unsigned v = (dreal + 3u) & ~3u;          // padded degree
    unsigned x = v;
    #pragma unroll
    for (int o = 1; o < 32; o <<= 1) {
        unsigned t = __shfl_up_sync(0xFFFFFFFFu, x, o);
        if (lane >= o) x += t;
    }
    __shared__ unsigned wsum[32];
    if (lane == 31) wsum[wid] = x;
    __syncthreads();
    if (wid == 0) {
        unsigned w = wsum[lane], orig = w;
        #pragma unroll
        for (int o = 1; o < 32; o <<= 1) {
            unsigned t = __shfl_up_sync(0xFFFFFFFFu, w, o);
            if (lane >= o) w += t;
        }
        wsum[lane] = w - orig;
    }
    __syncthreads();
    unsigned ex = (x - v) + wsum[wid] + g_boff[b];
    if (i < N) {
        g_rowptr[i] = (int)ex;
        g_cursor[i] = (int)ex;
        float fv = (float)dreal;
        g_dinv[i] = dreal ? rsqrtf(fv) : 0.f;
        g_dsq[i]  = dreal ? sqrtf(fv)  : 0.f;
        if (i == N - 1) g_rowptr[N] = (int)(ex + v);
    }
}

// ---------------------------------------------------------------------------
// fill CSR columns via edge symmetry: one thread handles the (u->i) and
// (i->u) directions of each interaction. Then pad rows to rounded degree.
// ---------------------------------------------------------------------------
__global__ void fill_kernel(const int* __restrict__ ei, int E, int Eh) {
    int e = blockIdx.x * blockDim.x + threadIdx.x;
    if (e >= Eh) return;
    int u = ldcs_i(ei + e);
    int i = ldcs_i(ei + E + e);
    int pi = atomicAdd(&g_cursor[i], 1);   // row i receives col u
    g_col[pi] = u;
    int pu = atomicAdd(&g_cursor[u], 1);   // row u receives col i
    g_col[pu] = i;
}

__global__ void pad_fill(int N) {
    int n = blockIdx.x * blockDim.x + threadIdx.x;
    if (n >= N) return;
    int cur = g_cursor[n];                 // rowptr[n] + real_deg
    int end = g_rowptr[n + 1];
    for (int j = cur; j < end; j++) g_col[j] = N;   // dummy zero row
}

// ---------------------------------------------------------------------------
// prescale: g_xA[n] = dinv[n] * concat(Gu, Gi)[n]   (float4 granularity)
// ---------------------------------------------------------------------------
__global__ void prescale_kernel(const float* __restrict__ Gu,
                                const float* __restrict__ Gi,
                                int U, int N) {
    long long i = (long long)blockIdx.x * blockDim.x + threadIdx.x;
    long long total4 = (long long)N * (D / 4);
    if (i >= total4) return;
    int node = (int)(i >> 4);
    long long ub4 = (long long)U * (D / 4);
    float4 v = (i < ub4) ? ((const float4*)Gu)[i]
                         : ((const float4*)Gi)[i - ub4];
    float di = __ldg(g_dinv + node);
    v.x *= di; v.y *= di; v.z *= di; v.w *= di;
    ((float4*)g_xA)[i] = v;
}

// ---------------------------------------------------------------------------
// Fused gather (unweighted sum of prescaled rows) + dinv_d scale + noise
// perturbation. Warp per node; lane holds float2. Degrees padded to a
// multiple of 4 -> pure 4-wide inner loop, no remainder (R11 structure).
// Streaming hints on single-use data keep L1 for hot x rows.
//   LAYER 0: read g_xA, write g_xB = s0*dinv            (no acc access)
//   LAYER 1: read g_xB, write g_xA = s1*dinv            (no acc access)
//   LAYER 2: read g_xA (gather) + own rows of g_xB/g_xA,
//            acc = (xB[n]*dsq + xA[n]*dsq + s2) / 3, re-zero g_deg
// ---------------------------------------------------------------------------
__device__ __forceinline__ float sgnf(float v) {
    return (v > 0.f) ? 1.f : ((v < 0.f) ? -1.f : 0.f);
}

template <int LAYER>
__global__ void gather_perturb(const float* __restrict__ noise,
                               float* __restrict__ acc, int N) {
    long long t = (long long)blockIdx.x * blockDim.x + threadIdx.x;
    int n = (int)(t >> 5);
    if (n >= N) return;
    int lane = threadIdx.x & 31;

    const float* x = (LAYER == 1) ? g_xB : g_xA;

    int beg = __ldg(g_rowptr + n);
    int end = __ldg(g_rowptr + n + 1);

    // hoist independent loads (noise is single-use -> streaming)
    float2 nv = ldcs_f2((const float2*)(noise + (long long)n * D) + lane);
    float  di = __ldg(g_dinv + n);

    float2 s = make_float2(0.f, 0.f);
    for (int j0 = beg; j0 < end; j0 += 32) {
        int jj = j0 + lane;
        int col = (jj < end) ? ldcs_i(g_col + jj) : 0;
        int cnt = min(32, end - j0);     // warp-uniform, multiple of 4
        for (int k = 0; k < cnt; k += 4) {
            int c0 = __shfl_sync(0xFFFFFFFFu, col, k);
            int c1 = __shfl_sync(0xFFFFFFFFu, col, k + 1);
            int c2 = __shfl_sync(0xFFFFFFFFu, col, k + 2);
            int c3 = __shfl_sync(0xFFFFFFFFu, col, k + 3);
            float2 v0 = __ldg((const float2*)(x + (long long)c0 * D) + lane);
            float2 v1 = __ldg((const float2*)(x + (long long)c1 * D) + lane);
            float2 v2 = __ldg((const float2*)(x + (long long)c2 * D) + lane);
            float2 v3 = __ldg((const float2*)(x + (long long)c3 * D) + lane);
            s.x += v0.x; s.y += v0.y;
            s.x += v1.x; s.y += v1.y;
            s.x += v2.x; s.y += v2.y;
            s.x += v3.x; s.y += v3.y;
        }
    }

    s.x *= di; s.y *= di;

    // perturb: s += sign(s) * (noise_row / max(||noise_row||,1e-12)) * EPS
    float ss = nv.x * nv.x + nv.y * nv.y;
    #pragma unroll
    for (int o = 16; o; o >>= 1) ss += __shfl_xor_sync(0xFFFFFFFFu, ss, o);
    float scale = EPSV / fmaxf(sqrtf(ss), 1e-12f);
    s.x += sgnf(s.x) * nv.x * scale;
    s.y += sgnf(s.y) * nv.y * scale;

    if (LAYER == 0) {
        ((float2*)(g_xB + (long long)n * D))[lane] =
            make_float2(s.x * di, s.y * di);
    } else if (LAYER == 1) {
        ((float2*)(g_xA + (long long)n * D))[lane] =
            make_float2(s.x * di, s.y * di);
    } else {
        // recover s0, s1 from stored prescaled rows: stored * sqrt(deg) ~= s
        float dq = __ldg(g_dsq + n);
        float2 b0 = ldcs_f2((const float2*)(g_xB + (long long)n * D) + lane);
        float2 a1 = ldcs_f2((const float2*)(g_xA + (long long)n * D) + lane);
        const float third = 1.f / 3.f;
        float2 av;
        av.x = (b0.x * dq + a1.x * dq + s.x) * third;
        av.y = (b0.y * dq + a1.y * dq + s.y) * third;
        stcs_f2((float2*)(acc + (long long)n * D) + lane, av);
        if (lane == 0) g_deg[n] = 0u;   // restore invariant
    }
}

// ---------------------------------------------------------------------------
extern "C" void kernel_launch(void* const* d_in, const int* in_sizes, int n_in,
                              void* d_out, int out_size) {
    const float* Gu = (const float*)d_in[0];
    const float* Gi = (const float*)d_in[1];
    const float* nz = (const float*)d_in[2];
    const int*   ei = (const int*)d_in[3];

    int U = in_sizes[0] / D;
    int I = in_sizes[1] / D;
    int N = U + I;
    int E = in_sizes[3] / 2;
    int Eh = E / 2;

    float* acc = (float*)d_out;

    const int TPB = 256;
    int blks_Eh = (Eh + TPB - 1) / TPB;
    int blks_N  = (N + TPB - 1) / TPB;
    int B       = (N + 1023) / 1024;
    long long total4 = (long long)N * (D / 4);
    int blks_p = (int)((total4 + TPB - 1) / TPB);
    long long node_threads = (long long)N * 32;
    int blks_g = (int)((node_threads + TPB - 1) / TPB);

    long long nd = (long long)N * D;

    deg_kernel<<<blks_Eh, TPB>>>(ei, E, Eh);
    tile_reduce<<<B, 1024>>>(N);
    scan_bsums<<<1, 1024>>>(B);
    emit_rowptr<<<B, 1024>>>(N);
    fill_kernel<<<blks_Eh, TPB>>>(ei, E, Eh);
    pad_fill<<<blks_N, TPB>>>(N);
    prescale_kernel<<<blks_p, TPB>>>(Gu, Gi, U, N);
    gather_perturb<0><<<blks_g, TPB>>>(nz,          acc, N);
    gather_perturb<1><<<blks_g, TPB>>>(nz + nd,     acc, N);
    gather_perturb<2><<<blks_g, TPB>>>(nz + 2 * nd, acc, N);
}

// round 14
// speedup vs baseline: 1.1487x; 1.0060x over previous
#include <cuda_runtime.h>

#define D     64
#define EPSV  0.1f
#define MAXN  225000
#define MAXE  4000000          // E + 3*N padding headroom
#define MAXEH 1600000          // interactions (E/2)
#define NBLK  512

// Scratch (no allocations allowed). Zero-initialized at module load.
// INVARIANT: g_deg is all-zero on entry to kernel_launch; gather<2>
// re-zeroes it, so the invariant holds across calls/graph replays.
// Row MAXN (== N) of g_xA/g_xB is the dummy zero row (never written).
__device__ float        g_xA[(MAXN + 1) * D];  // prescaled layer input
__device__ float        g_xB[(MAXN + 1) * D];
__device__ float        g_dinv[MAXN];     // 1/sqrt(deg)  (0 for deg==0)
__device__ float        g_dsq[MAXN];      // sqrt(deg)    (0 for deg==0)
__device__ unsigned int g_deg[MAXN];
__device__ unsigned int g_bsum[NBLK];
__device__ unsigned int g_boff[NBLK];
__device__ int          g_rowptr[MAXN + 1];   // padded offsets (deg rounded to 4)
__device__ int2         g_rank[MAXEH];    // {rank in item row, rank in user row}
__device__ int          g_col[MAXE];      // CSR columns (src node per edge)

__device__ __forceinline__ int   ldcs_i(const int* p)   {
    int v; asm("ld.global.cs.b32 %0, [%1];" : "=r"(v) : "l"(p)); return v;
}
__device__ __forceinline__ float2 ldcs_f2(const float2* p) {
    float2 v;
    asm("ld.global.cs.v2.f32 {%0,%1}, [%2];" : "=f"(v.x), "=f"(v.y) : "l"(p));
    return v;
}
__device__ __forceinline__ void stcs_f2(float2* p, float2 v) {
    asm("st.global.cs.v2.f32 [%0], {%1,%2};" :: "l"(p), "f"(v.x), "f"(v.y));
}

// ---------------------------------------------------------------------------
// degree + rank: edge e (e < E/2) is (u -> i); its mirror is (i -> u).
// The atomicAdd return IS the edge's rank within each destination row.
// ---------------------------------------------------------------------------
__global__ void deg_rank_kernel(const int* __restrict__ ei, int E, int Eh) {
    int e = blockIdx.x * blockDim.x + threadIdx.x;
    if (e >= Eh) return;
    int u = ldcs_i(ei + e);            // user endpoint
    int i = ldcs_i(ei + E + e);        // item endpoint
    unsigned ri = atomicAdd(&g_deg[i], 1u);   // rank of col u in row i
    unsigned ru = atomicAdd(&g_deg[u], 1u);   // rank of col i in row u
    g_rank[e] = make_int2((int)ri, (int)ru);
}

// ---------------------------------------------------------------------------
// Coalesced 3-kernel exclusive scan of PADDED degrees -> g_rowptr.
// deg4 = (deg+3) & ~3. dinv/dsq from real degree; pad slots written here.
// ---------------------------------------------------------------------------
__global__ void tile_reduce(int N) {
    int i = blockIdx.x * 1024 + threadIdx.x;
    int lane = threadIdx.x & 31, wid = threadIdx.x >> 5;
    unsigned v = (i < N) ? ((g_deg[i] + 3u) & ~3u) : 0u;
    #pragma unroll
    for (int o = 16; o; o >>= 1) v += __shfl_down_sync(0xFFFFFFFFu, v, o);
    __shared__ unsigned ws[32];
    if (lane == 0) ws[wid] = v;
    __syncthreads();
    if (wid == 0) {
        v = ws[lane];
        #pragma unroll
        for (int o = 16; o; o >>= 1) v += __shfl_down_sync(0xFFFFFFFFu, v, o);
        if (lane == 0) g_bsum[blockIdx.x] = v;
    }
}

__global__ void scan_bsums(int B) {           // single block, 1024 threads
    __shared__ unsigned sh[1024];
    int tid = threadIdx.x;
    unsigned v = (tid < B) ? g_bsum[tid] : 0u;
    sh[tid] = v;
    __syncthreads();
    for (int off = 1; off < 1024; off <<= 1) {
        unsigned t = (tid >= off) ? sh[tid - off] : 0u;
        __syncthreads();
        sh[tid] += t;
        __syncthreads();
    }
    if (tid < B) g_boff[tid] = sh[tid] - v;   // exclusive
}

__global__ void emit_rowptr(int N) {
    int b = blockIdx.x, tid = threadIdx.x;
    int lane = tid & 31, wid = tid >> 5;
    int i = b * 1024 + tid;
    unsigned dreal = (i < N) ? g_deg[i] : 0u;
    unsigned v = (dreal + 3u) & ~3u;          // padded degree
    unsigned x = v;
    #pragma unroll
    for (int o = 1; o < 32; o <<= 1) {
        unsigned t = __shfl_up_sync(0xFFFFFFFFu, x, o);
        if (lane >= o) x += t;
    }
    __shared__ unsigned wsum[32];
    if (lane == 31) wsum[wid] = x;
    __syncthreads();
    if (wid == 0) {
        unsigned w = wsum[lane], orig = w;
        #pragma unroll
        for (int o = 1; o < 32; o <<= 1) {
            unsigned t = __shfl_up_sync(0xFFFFFFFFu, w, o);
            if (lane >= o) w += t;
        }
        wsum[lane] = w - orig;
    }
    __syncthreads();
    unsigned ex = (x - v) + wsum[wid] + g_boff[b];
    if (i < N) {
        g_rowptr[i] = (int)ex;
        float fv = (float)dreal;
        g_dinv[i] = dreal ? rsqrtf(fv) : 0.f;
        g_dsq[i]  = dreal ? sqrtf(fv)  : 0.f;
        // write pad slots (<= 3) with the sentinel zero-row index N
        for (unsigned j = ex + dreal; j < ex + v; j++) g_col[j] = N;
        if (i == N - 1) g_rowptr[N] = (int)(ex + v);
    }
}

// ---------------------------------------------------------------------------
// fill CSR columns — NO atomics: position = rowptr[dst] + precomputed rank.
// ---------------------------------------------------------------------------
__global__ void fill_kernel(const int* __restrict__ ei, int E, int Eh) {
    int e = blockIdx.x * blockDim.x + threadIdx.x;
    if (e >= Eh) return;
    int u = ldcs_i(ei + e);
    int i = ldcs_i(ei + E + e);
    int2 r = g_rank[e];
    g_col[__ldg(g_rowptr + i) + r.x] = u;   // row i receives col u
    g_col[__ldg(g_rowptr + u) + r.y] = i;   // row u receives col i
}

// ---------------------------------------------------------------------------
// prescale: g_xA[n] = dinv[n] * concat(Gu, Gi)[n]   (float4 granularity)
// ---------------------------------------------------------------------------
__global__ void prescale_kernel(const float* __restrict__ Gu,
                                const float* __restrict__ Gi,
                                int U, int N) {
    long long i = (long long)blockIdx.x * blockDim.x + threadIdx.x;
    long long total4 = (long long)N * (D / 4);
    if (i >= total4) return;
    int node = (int)(i >> 4);
    long long ub4 = (long long)U * (D / 4);
    float4 v = (i < ub4) ? ((const float4*)Gu)[i]
                         : ((const float4*)Gi)[i - ub4];
    float di = __ldg(g_dinv + node);
    v.x *= di; v.y *= di; v.z *= di; v.w *= di;
    ((float4*)g_xA)[i] = v;
}

// ---------------------------------------------------------------------------
// Fused gather (unweighted sum of prescaled rows) + dinv_d scale + noise
// perturbation. Warp per node; lane holds float2. Degrees padded to a
// multiple of 4 -> pure 4-wide inner loop, no remainder.
//   LAYER 0: read g_xA, write g_xB = s0*dinv            (no acc access)
//   LAYER 1: read g_xB, write g_xA = s1*dinv            (no acc access)
//   LAYER 2: read g_xA (gather) + own rows of g_xB/g_xA,
//            acc = (xB[n]*dsq + xA[n]*dsq + s2) / 3, re-zero g_deg
// ---------------------------------------------------------------------------
__device__ __forceinline__ float sgnf(float v) {
    return (v > 0.f) ? 1.f : ((v < 0.f) ? -1.f : 0.f);
}

template <int LAYER>
__global__ void gather_perturb(const float* __restrict__ noise,
                               float* __restrict__ acc, int N) {
    long long t = (long long)blockIdx.x * blockDim.x + threadIdx.x;
    int n = (int)(t >> 5);
    if (n >= N) return;
    int lane = threadIdx.x & 31;

    const float* x = (LAYER == 1) ? g_xB : g_xA;

    int beg = __ldg(g_rowptr + n);
    int end = __ldg(g_rowptr + n + 1);

    // hoist independent loads (noise is single-use -> streaming)
    float2 nv = ldcs_f2((const float2*)(noise + (long long)n * D) + lane);
    float  di = __ldg(g_dinv + n);

    float2 s = make_float2(0.f, 0.f);
    for (int j0 = beg; j0 < end; j0 += 32) {
        int jj = j0 + lane;
        int col = (jj < end) ? ldcs_i(g_col + jj) : 0;
        int cnt = min(32, end - j0);     // warp-uniform, multiple of 4
        for (int k = 0; k < cnt; k += 4) {
            int c0 = __shfl_sync(0xFFFFFFFFu, col, k);
            int c1 = __shfl_sync(0xFFFFFFFFu, col, k + 1);
            int c2 = __shfl_sync(0xFFFFFFFFu, col, k + 2);
            int c3 = __shfl_sync(0xFFFFFFFFu, col, k + 3);
            float2 v0 = __ldg((const float2*)(x + (long long)c0 * D) + lane);
            float2 v1 = __ldg((const float2*)(x + (long long)c1 * D) + lane);
            float2 v2 = __ldg((const float2*)(x + (long long)c2 * D) + lane);
            float2 v3 = __ldg((const float2*)(x + (long long)c3 * D) + lane);
            s.x += v0.x; s.y += v0.y;
            s.x += v1.x; s.y += v1.y;
            s.x += v2.x; s.y += v2.y;
            s.x += v3.x; s.y += v3.y;
        }
    }

    s.x *= di; s.y *= di;

    // perturb: s += sign(s) * (noise_row / max(||noise_row||,1e-12)) * EPS
    float ss = nv.x * nv.x + nv.y * nv.y;
    #pragma unroll
    for (int o = 16; o; o >>= 1) ss += __shfl_xor_sync(0xFFFFFFFFu, ss, o);
    float scale = EPSV / fmaxf(sqrtf(ss), 1e-12f);
    s.x += sgnf(s.x) * nv.x * scale;
    s.y += sgnf(s.y) * nv.y * scale;

    if (LAYER == 0) {
        ((float2*)(g_xB + (long long)n * D))[lane] =
            make_float2(s.x * di, s.y * di);
    } else if (LAYER == 1) {
        ((float2*)(g_xA + (long long)n * D))[lane] =
            make_float2(s.x * di, s.y * di);
    } else {
        // recover s0, s1 from stored prescaled rows: stored * sqrt(deg) ~= s
        float dq = __ldg(g_dsq + n);
        float2 b0 = ldcs_f2((const float2*)(g_xB + (long long)n * D) + lane);
        float2 a1 = ldcs_f2((const float2*)(g_xA + (long long)n * D) + lane);
        const float third = 1.f / 3.f;
        float2 av;
        av.x = (b0.x * dq + a1.x * dq + s.x) * third;
        av.y = (b0.y * dq + a1.y * dq + s.y) * third;
        stcs_f2((float2*)(acc + (long long)n * D) + lane, av);
        if (lane == 0) g_deg[n] = 0u;   // restore invariant
    }
}

// ---------------------------------------------------------------------------
extern "C" void kernel_launch(void* const* d_in, const int* in_sizes, int n_in,
                              void* d_out, int out_size) {
    const float* Gu = (const float*)d_in[0];
    const float* Gi = (const float*)d_in[1];
    const float* nz = (const float*)d_in[2];
    const int*   ei = (const int*)d_in[3];

    int U = in_sizes[0] / D;
    int I = in_sizes[1] / D;
    int N = U + I;
    int E = in_sizes[3] / 2;
    int Eh = E / 2;

    float* acc = (float*)d_out;

    const int TPB = 256;
    int blks_Eh = (Eh + TPB - 1) / TPB;
    int B       = (N + 1023) / 1024;
    long long total4 = (long long)N * (D / 4);
    int blks_p = (int)((total4 + TPB - 1) / TPB);
    long long node_threads = (long long)N * 32;
    int blks_g = (int)((node_threads + TPB - 1) / TPB);

    long long nd = (long long)N * D;

    deg_rank_kernel<<<blks_Eh, TPB>>>(ei, E, Eh);
    tile_reduce<<<B, 1024>>>(N);
    scan_bsums<<<1, 1024>>>(B);
    emit_rowptr<<<B, 1024>>>(N);
    fill_kernel<<<blks_Eh, TPB>>>(ei, E, Eh);
    prescale_kernel<<<blks_p, TPB>>>(Gu, Gi, U, N);
    gather_perturb<0><<<blks_g, TPB>>>(nz,          acc, N);
    gather_perturb<1><<<blks_g, TPB>>>(nz + nd,     acc, N);
    gather_perturb<2><<<blks_g, TPB>>>(nz + 2 * nd, acc, N);
}

// round 15
// speedup vs baseline: 1.1713x; 1.0197x over previous
#include <cuda_runtime.h>

#define D     64
#define EPSV  0.1f
#define MAXN  225000
#define MAXE  4000000          // E + 3*N padding headroom
#define MAXEH 1600000          // interactions (E/2)
#define NBLK  512

// Scratch (no allocations allowed). Zero-initialized at module load.
// INVARIANT: g_deg is all-zero on entry to kernel_launch; gather<2>
// re-zeroes it, so the invariant holds across calls/graph replays.
// Row MAXN (== N) of g_xA/g_xB is the dummy zero row (never written).
__device__ float        g_xA[(MAXN + 1) * D];  // prescaled layer input
__device__ float        g_xB[(MAXN + 1) * D];
__device__ float        g_dinv[MAXN];     // 1/sqrt(deg)  (0 for deg==0)
__device__ float        g_dsq[MAXN];      // sqrt(deg)    (0 for deg==0)
__device__ unsigned int g_deg[MAXN];
__device__ unsigned int g_bsum[NBLK];
__device__ unsigned int g_boff[NBLK];
__device__ int          g_rowptr[MAXN + 1];   // padded offsets (deg rounded to 4)
__device__ int2         g_rank[MAXEH];    // {rank in item row, rank in user row}
__device__ int          g_col[MAXE];      // CSR columns (src node per edge)

__device__ __forceinline__ int   ldcs_i(const int* p)   {
    int v; asm("ld.global.cs.b32 %0, [%1];" : "=r"(v) : "l"(p)); return v;
}
__device__ __forceinline__ float2 ldcs_f2(const float2* p) {
    float2 v;
    asm("ld.global.cs.v2.f32 {%0,%1}, [%2];" : "=f"(v.x), "=f"(v.y) : "l"(p));
    return v;
}
__device__ __forceinline__ void stcs_f2(float2* p, float2 v) {
    asm("st.global.cs.v2.f32 [%0], {%1,%2};" :: "l"(p), "f"(v.x), "f"(v.y));
}

// ---------------------------------------------------------------------------
// degree + rank: edge e (e < E/2) is (u -> i); its mirror is (i -> u).
// The atomicAdd return IS the edge's rank within each destination row.
// ---------------------------------------------------------------------------
__global__ void deg_rank_kernel(const int* __restrict__ ei, int E, int Eh) {
    int e = blockIdx.x * blockDim.x + threadIdx.x;
    if (e >= Eh) return;
    int u = ldcs_i(ei + e);            // user endpoint
    int i = ldcs_i(ei + E + e);        // item endpoint
    unsigned ri = atomicAdd(&g_deg[i], 1u);   // rank of col u in row i
    unsigned ru = atomicAdd(&g_deg[u], 1u);   // rank of col i in row u
    g_rank[e] = make_int2((int)ri, (int)ru);
}

// ---------------------------------------------------------------------------
// Coalesced 3-kernel exclusive scan of PADDED degrees -> g_rowptr.
// deg4 = (deg+3) & ~3. dinv/dsq from real degree; pad slots written here.
// ---------------------------------------------------------------------------
__global__ void tile_reduce(int N) {
    int i = blockIdx.x * 1024 + threadIdx.x;
    int lane = threadIdx.x & 31, wid = threadIdx.x >> 5;
    unsigned v = (i < N) ? ((g_deg[i] + 3u) & ~3u) : 0u;
    #pragma unroll
    for (int o = 16; o; o >>= 1) v += __shfl_down_sync(0xFFFFFFFFu, v, o);
    __shared__ unsigned ws[32];
    if (lane == 0) ws[wid] = v;
    __syncthreads();
    if (wid == 0) {
        v = ws[lane];
        #pragma unroll
        for (int o = 16; o; o >>= 1) v += __shfl_down_sync(0xFFFFFFFFu, v, o);
        if (lane == 0) g_bsum[blockIdx.x] = v;
    }
}

__global__ void scan_bsums(int B) {           // single block, 1024 threads
    __shared__ unsigned sh[1024];
    int tid = threadIdx.x;
    unsigned v = (tid < B) ? g_bsum[tid] : 0u;
    sh[tid] = v;
    __syncthreads();
    for (int off = 1; off < 1024; off <<= 1) {
        unsigned t = (tid >= off) ? sh[tid - off] : 0u;
        __syncthreads();
        sh[tid] += t;
        __syncthreads();
    }
    if (tid < B) g_boff[tid] = sh[tid] - v;   // exclusive
}

__global__ void emit_rowptr(int N) {
    int b = blockIdx.x, tid = threadIdx.x;
    int lane = tid & 31, wid = tid >> 5;
    int i = b * 1024 + tid;
    unsigned dreal = (i < N) ? g_deg[i] : 0u;
    unsigned v = (dreal + 3u) & ~3u;          // padded degree
    unsigned x = v;
    #pragma unroll
    for (int o = 1; o < 32; o <<= 1) {
        unsigned t = __shfl_up_sync(0xFFFFFFFFu, x, o);
        if (lane >= o) x += t;
    }
    __shared__ unsigned wsum[32];
    if (lane == 31) wsum[wid] = x;
    __syncthreads();
    if (wid == 0) {
        unsigned w = wsum[lane], orig = w;
        #pragma unroll
        for (int o = 1; o < 32; o <<= 1) {
            unsigned t = __shfl_up_sync(0xFFFFFFFFu, w, o);
            if (lane >= o) w += t;
        }
        wsum[lane] = w - orig;
    }
    __syncthreads();
    unsigned ex = (x - v) + wsum[wid] + g_boff[b];
    if (i < N) {
        g_rowptr[i] = (int)ex;
        float fv = (float)dreal;
        g_dinv[i] = dreal ? rsqrtf(fv) : 0.f;
        g_dsq[i]  = dreal ? sqrtf(fv)  : 0.f;
        // write pad slots (<= 3) with the sentinel zero-row index N
        for (unsigned j = ex + dreal; j < ex + v; j++) g_col[j] = N;
        if (i == N - 1) g_rowptr[N] = (int)(ex + v);
    }
}

// ---------------------------------------------------------------------------
// Fused fill + prescale: both depend only on emit_rowptr and are mutually
// independent, so one kernel runs them concurrently via block-range split.
//   blocks [0, blksP):      prescale  g_xA = dinv * concat(Gu,Gi)
//   blocks [blksP, gridDim): fill     g_col[rowptr[dst]+rank] = src
// ---------------------------------------------------------------------------
__global__ void fill_prescale(const float* __restrict__ Gu,
                              const float* __restrict__ Gi,
                              const int* __restrict__ ei,
                              int U, int N, int E, int Eh, int blksP) {
    if (blockIdx.x < blksP) {
        long long i = (long long)blockIdx.x * blockDim.x + threadIdx.x;
        long long total4 = (long long)N * (D / 4);
        if (i >= total4) return;
        int node = (int)(i >> 4);
        long long ub4 = (long long)U * (D / 4);
        float4 v = (i < ub4) ? ((const float4*)Gu)[i]
                             : ((const float4*)Gi)[i - ub4];
        float di = __ldg(g_dinv + node);
        v.x *= di; v.y *= di; v.z *= di; v.w *= di;
        ((float4*)g_xA)[i] = v;
    } else {
        int e = (blockIdx.x - blksP) * blockDim.x + threadIdx.x;
        if (e >= Eh) return;
        int u = ldcs_i(ei + e);
        int i = ldcs_i(ei + E + e);
        int2 r = g_rank[e];
        g_col[__ldg(g_rowptr + i) + r.x] = u;   // row i receives col u
        g_col[__ldg(g_rowptr + u) + r.y] = i;   // row u receives col i
    }
}

// ---------------------------------------------------------------------------
// Fused gather (unweighted sum of prescaled rows) + dinv_d scale + noise
// perturbation. Warp per node; lane holds float2. Degrees padded to a
// multiple of 4 -> pure 4-wide inner loop, no remainder.
//   LAYER 0: read g_xA, write g_xB = s0*dinv            (no acc access)
//   LAYER 1: read g_xB, write g_xA = s1*dinv            (no acc access)
//   LAYER 2: read g_xA (gather) + own rows of g_xB/g_xA,
//            acc = (xB[n]*dsq + xA[n]*dsq + s2) / 3, re-zero g_deg
// ---------------------------------------------------------------------------
__device__ __forceinline__ float sgnf(float v) {
    return (v > 0.f) ? 1.f : ((v < 0.f) ? -1.f : 0.f);
}

template <int LAYER>
__global__ void gather_perturb(const float* __restrict__ noise,
                               float* __restrict__ acc, int N) {
    long long t = (long long)blockIdx.x * blockDim.x + threadIdx.x;
    int n = (int)(t >> 5);
    if (n >= N) return;
    int lane = threadIdx.x & 31;

    const float* x = (LAYER == 1) ? g_xB : g_xA;

    int beg = __ldg(g_rowptr + n);
    int end = __ldg(g_rowptr + n + 1);

    // hoist independent loads (noise is single-use -> streaming)
    float2 nv = ldcs_f2((const float2*)(noise + (long long)n * D) + lane);
    float  di = __ldg(g_dinv + n);

    float2 s = make_float2(0.f, 0.f);
    for (int j0 = beg; j0 < end; j0 += 32) {
        int jj = j0 + lane;
        int col = (jj < end) ? ldcs_i(g_col + jj) : 0;
        int cnt = min(32, end - j0);     // warp-uniform, multiple of 4
        for (int k = 0; k < cnt; k += 4) {
            int c0 = __shfl_sync(0xFFFFFFFFu, col, k);
            int c1 = __shfl_sync(0xFFFFFFFFu, col, k + 1);
            int c2 = __shfl_sync(0xFFFFFFFFu, col, k + 2);
            int c3 = __shfl_sync(0xFFFFFFFFu, col, k + 3);
            float2 v0 = __ldg((const float2*)(x + (long long)c0 * D) + lane);
            float2 v1 = __ldg((const float2*)(x + (long long)c1 * D) + lane);
            float2 v2 = __ldg((const float2*)(x + (long long)c2 * D) + lane);
            float2 v3 = __ldg((const float2*)(x + (long long)c3 * D) + lane);
            s.x += v0.x; s.y += v0.y;
            s.x += v1.x; s.y += v1.y;
            s.x += v2.x; s.y += v2.y;
            s.x += v3.x; s.y += v3.y;
        }
    }

    s.x *= di; s.y *= di;

    // perturb: s += sign(s) * (noise_row / max(||noise_row||,1e-12)) * EPS
    float ss = nv.x * nv.x + nv.y * nv.y;
    #pragma unroll
    for (int o = 16; o; o >>= 1) ss += __shfl_xor_sync(0xFFFFFFFFu, ss, o);
    float scale = EPSV / fmaxf(sqrtf(ss), 1e-12f);
    s.x += sgnf(s.x) * nv.x * scale;
    s.y += sgnf(s.y) * nv.y * scale;

    if (LAYER == 0) {
        ((float2*)(g_xB + (long long)n * D))[lane] =
            make_float2(s.x * di, s.y * di);
    } else if (LAYER == 1) {
        ((float2*)(g_xA + (long long)n * D))[lane] =
            make_float2(s.x * di, s.y * di);
    } else {
        // recover s0, s1 from stored prescaled rows: stored * sqrt(deg) ~= s
        float dq = __ldg(g_dsq + n);
        float2 b0 = ldcs_f2((const float2*)(g_xB + (long long)n * D) + lane);
        float2 a1 = ldcs_f2((const float2*)(g_xA + (long long)n * D) + lane);
        const float third = 1.f / 3.f;
        float2 av;
        av.x = (b0.x * dq + a1.x * dq + s.x) * third;
        av.y = (b0.y * dq + a1.y * dq + s.y) * third;
        stcs_f2((float2*)(acc + (long long)n * D) + lane, av);
        if (lane == 0) g_deg[n] = 0u;   // restore invariant
    }
}

// ---------------------------------------------------------------------------
extern "C" void kernel_launch(void* const* d_in, const int* in_sizes, int n_in,
                              void* d_out, int out_size) {
    const float* Gu = (const float*)d_in[0];
    const float* Gi = (const float*)d_in[1];
    const float* nz = (const float*)d_in[2];
    const int*   ei = (const int*)d_in[3];

    int U = in_sizes[0] / D;
    int I = in_sizes[1] / D;
    int N = U + I;
    int E = in_sizes[3] / 2;
    int Eh = E / 2;

    float* acc = (float*)d_out;

    const int TPB = 256;
    int blks_Eh = (Eh + TPB - 1) / TPB;
    int B       = (N + 1023) / 1024;
    long long total4 = (long long)N * (D / 4);
    int blks_p = (int)((total4 + TPB - 1) / TPB);
    long long node_threads = (long long)N * 32;
    int blks_g = (int)((node_threads + TPB - 1) / TPB);

    long long nd = (long long)N * D;

    deg_rank_kernel<<<blks_Eh, TPB>>>(ei, E, Eh);
    tile_reduce<<<B, 1024>>>(N);
    scan_bsums<<<1, 1024>>>(B);
    emit_rowptr<<<B, 1024>>>(N);
    fill_prescale<<<blks_p + blks_Eh, TPB>>>(Gu, Gi, ei, U, N, E, Eh, blks_p);
    gather_perturb<0><<<blks_g, TPB>>>(nz,          acc, N);
    gather_perturb<1><<<blks_g, TPB>>>(nz + nd,     acc, N);
    gather_perturb<2><<<blks_g, TPB>>>(nz + 2 * nd, acc, N);
}